// round 9
// baseline (speedup 1.0000x reference)
#include <cuda_runtime.h>
#include <cuda_fp16.h>
#include <cstdint>

// Problem dims
#define N_SAMPLES 2048
#define D_FEAT    64
#define P_PAIRS   2016
#define INNER     32
#define KDIM      64512   // P_PAIRS * INNER
#define HIDDEN    2048
#define CLASSES   10

// GEMM tiling
#define BM 128
#define BN 256
#define BK 64
#define STG 4
#define CHUNKS (KDIM / BK)                 // 1008
#define A_STAGE (BM * 128)                 // 16384 B
#define B_STAGE (BN * 128)                 // 32768 B
#define STAGE_B (A_STAGE + B_STAGE)        // 49152 B
#define OFF_MBAR (STG * STAGE_B)           // 196608
#define SMEM_GEMM (OFF_MBAR + 64)

// -------------------- scratch (device globals; no allocation) --------------------
__device__ __half g_u [(size_t)N_SAMPLES * KDIM];   // tiled [mb][c][row][kc^sw] (A stages contiguous)
__device__ __half g_bt[(size_t)HIDDEN    * KDIM];   // tiled [nb][c][row][kc^sw] (B stages contiguous)
__device__ float  g_v [(size_t)N_SAMPLES * HIDDEN];
__device__ float  g_xT[(size_t)D_FEAT * N_SAMPLES];
__device__ int    g_ready_a[CHUNKS];                // target 2 per chunk
__device__ int    g_ready_b[8 * CHUNKS];            // target 8 per (nb, chunk)

// -------------------- helpers --------------------
__device__ __forceinline__ uint32_t smem_u32(const void* p) {
    return (uint32_t)__cvta_generic_to_shared(p);
}
__device__ __forceinline__ void mbar_init(uint32_t addr, uint32_t count) {
    asm volatile("mbarrier.init.shared.b64 [%0], %1;" :: "r"(addr), "r"(count) : "memory");
}
__device__ __forceinline__ void mbar_expect_tx(uint32_t addr, uint32_t bytes) {
    asm volatile("mbarrier.arrive.expect_tx.shared.b64 _, [%0], %1;"
                 :: "r"(addr), "r"(bytes) : "memory");
}
__device__ __forceinline__ void mbar_arrive(uint32_t addr) {
    asm volatile("mbarrier.arrive.shared.b64 _, [%0];" :: "r"(addr) : "memory");
}
__device__ __forceinline__ void mbar_wait(uint32_t addr, uint32_t parity) {
    uint32_t done;
    asm volatile(
        "{\n\t.reg .pred p;\n\t"
        "mbarrier.try_wait.parity.acquire.cta.shared::cta.b64 p, [%1], %2;\n\t"
        "selp.b32 %0, 1, 0, p;\n\t}"
        : "=r"(done) : "r"(addr), "r"(parity) : "memory");
    if (!done) {
        asm volatile(
            "{\n\t.reg .pred P1;\n\t"
            "W_%=:\n\t"
            "mbarrier.try_wait.parity.acquire.cta.shared::cta.b64 P1, [%0], %1, 0x989680;\n\t"
            "@P1 bra.uni D_%=;\n\t"
            "bra.uni W_%=;\n\t"
            "D_%=:\n\t}"
            :: "r"(addr), "r"(parity) : "memory");
    }
}
__device__ __forceinline__ void bulk_g2s(uint32_t dstSmem, const void* srcGmem,
                                         uint32_t bytes, uint32_t mbar) {
    asm volatile(
        "cp.async.bulk.shared::cluster.global.mbarrier::complete_tx::bytes [%0], [%1], %2, [%3];"
        :: "r"(dstSmem), "l"(srcGmem), "r"(bytes), "r"(mbar) : "memory");
}
__device__ __forceinline__ void ldsm_x4(uint32_t* r, uint32_t addr) {
    asm volatile("ldmatrix.sync.aligned.m8n8.x4.shared.b16 {%0,%1,%2,%3}, [%4];"
                 : "=r"(r[0]), "=r"(r[1]), "=r"(r[2]), "=r"(r[3]) : "r"(addr));
}
__device__ __forceinline__ void mma16816(float* c, const uint32_t* a, const uint32_t* b) {
    asm volatile(
        "mma.sync.aligned.m16n8k16.row.col.f32.f16.f16.f32 "
        "{%0,%1,%2,%3}, {%4,%5,%6,%7}, {%8,%9}, {%0,%1,%2,%3};"
        : "+f"(c[0]), "+f"(c[1]), "+f"(c[2]), "+f"(c[3])
        : "r"(a[0]), "r"(a[1]), "r"(a[2]), "r"(a[3]), "r"(b[0]), "r"(b[1]));
}
__device__ __forceinline__ uint32_t sw_off(int row, int kc) {
    return (uint32_t)(row * 128 + ((kc ^ (row & 7)) << 4));
}
// producer-side wait: chunk c's A slab and this CTA's B slab produced
__device__ __forceinline__ void spin_ready(int c, int nb) {
    volatile int* ra = g_ready_a + c;
    volatile int* rb = g_ready_b + nb * CHUNKS + c;
    while (*ra < 2) __nanosleep(128);
    while (*rb < 8) __nanosleep(128);
    __threadfence();
}

// ==================== kernel 1: transpose x ====================
__global__ void k_transpose_x(const float* __restrict__ x) {
    int idx = blockIdx.x * blockDim.x + threadIdx.x;
    if (idx < N_SAMPLES * D_FEAT) {
        int n = idx >> 6, d = idx & 63;
        g_xT[(size_t)d * N_SAMPLES + n] = x[idx];
    }
}

// ==================== kernel 2: prep, chunk-ordered (runs concurrent with GEMM) ====================
// 1008 chunk-groups x 66 blocks: sub 0,1 = pairwise MLP for pairs 2c, 2c+1 (full A slab of chunk c);
// sub 2..65 = Wv conv blocks (32 nt x 2 kt) for chunk c. Flags bumped on completion.
#define PREP_BLOCKS (CHUNKS * 66)

__global__ void k_prep(const float* __restrict__ Wu, const float* __restrict__ bu,
                       const float* __restrict__ Wv) {
    int tid = threadIdx.x;
    int c = blockIdx.x / 66;
    int sub = blockIdx.x % 66;

    if (sub < 2) {
        int p = c * 2 + sub;
        int a = 0, rem = p;
        while (rem >= (D_FEAT - 1 - a)) { rem -= (D_FEAT - 1 - a); a++; }
        int b = a + 1 + rem;

        __shared__ float w0[INNER], w1[INNER], bb[INNER];
        if (tid < INNER) {
            w0[tid] = Wu[(size_t)p * 2 * INNER + tid];
            w1[tid] = Wu[(size_t)p * 2 * INNER + INNER + tid];
            bb[tid] = bu[(size_t)p * INNER + tid];
        }
        __syncthreads();

        int h = sub;           // which half of the 128B row
        uint4* g_u_u4 = reinterpret_cast<uint4*>(g_u);
        const float* xa = g_xT + (size_t)a * N_SAMPLES;
        const float* xb = g_xT + (size_t)b * N_SAMPLES;
        for (int n = tid; n < N_SAMPLES; n += blockDim.x) {
            float va = xa[n], vb = xb[n];
            __half2 outv[INNER / 2];
            #pragma unroll
            for (int i = 0; i < INNER; i += 2) {
                float r0 = fmaf(va, w0[i],     fmaf(vb, w1[i],     bb[i]));
                float r1 = fmaf(va, w0[i + 1], fmaf(vb, w1[i + 1], bb[i + 1]));
                outv[i / 2] = __floats2half2_rn(fmaxf(r0, 0.f), fmaxf(r1, 0.f));
            }
            const uint4* src = reinterpret_cast<const uint4*>(outv);
            int mb = n >> 7, row = n & 127;
            size_t base8 = ((size_t)(mb * CHUNKS + c) * 128 + row) * 8;
            #pragma unroll
            for (int q = 0; q < 4; q++) {
                int kc = h * 4 + q;
                g_u_u4[base8 + (kc ^ (row & 7))] = src[q];
            }
        }
        __threadfence();
        __syncthreads();
        if (tid == 0) atomicAdd(&g_ready_a[c], 1);
    } else {
        int ci = sub - 2;
        int kt0 = c * 64 + (ci & 1) * 32;     // 32-deep K tile
        int nt0 = (ci >> 1) * 64;             // 64-wide N tile
        __shared__ float tile[32][65];
        #pragma unroll
        for (int pass = 0; pass < 8; pass++) {
            int idx = tid + pass * 256;
            int kl = idx >> 6, nl = idx & 63;
            tile[kl][nl] = Wv[(size_t)(kt0 + kl) * HIDDEN + nt0 + nl];
        }
        __syncthreads();
        int nl = tid >> 2, uq = tid & 3;
        __half hp[8];
        #pragma unroll
        for (int j = 0; j < 8; j++) hp[j] = __float2half(tile[uq * 8 + j][nl]);
        int n = nt0 + nl;
        int nb = n >> 8, rowB = n & 255;
        int kcq = ((kt0 & 63) >> 3) + uq;
        size_t unit = ((size_t)(nb * CHUNKS + c) * 256 + rowB) * 8 + (kcq ^ (rowB & 7));
        reinterpret_cast<uint4*>(g_bt)[unit] = *reinterpret_cast<uint4*>(hp);
        __threadfence();
        __syncthreads();
        if (tid == 0) atomicAdd(&g_ready_b[(nt0 >> 8) * CHUNKS + c], 1);
    }
}

// ==================== kernel 3: big GEMM v = relu(u @ Wv + bv) ====================
// R6 structure (best): 16 warps 64x32 tiles, warp0 lane0 = bulk-TMA producer,
// mbarrier pipeline, no mainloop syncthreads. Producer spins on chunk-ready flags.
__global__ void __launch_bounds__(512, 1) k_gemm(const float* __restrict__ bv) {
    extern __shared__ char smem[];
    uint32_t sbase = smem_u32(smem);
    int tid = threadIdx.x;
    int lane = tid & 31;
    int wid = tid >> 5;          // 0..15
    int wm = wid >> 3;           // 0..1  (64 rows each)
    int wn = wid & 7;            // 0..7  (32 cols each)
    int nb = blockIdx.x;         // 8 n-blocks
    int mb = blockIdx.y;         // 16 m-blocks

    const char* gA = (const char*)g_u  + (size_t)mb * CHUNKS * A_STAGE;
    const char* gB = (const char*)g_bt + (size_t)nb * CHUNKS * B_STAGE;

    uint32_t mfull = sbase + OFF_MBAR;
    uint32_t mempty = sbase + OFF_MBAR + 32;
    if (tid == 0) {
        #pragma unroll
        for (int s = 0; s < STG; s++) {
            mbar_init(mfull + s * 8, 1);
            mbar_init(mempty + s * 8, 16);
        }
    }
    __syncthreads();

    // prologue: fill stages 0..STG-2 (wait for prep to produce them first)
    if (tid == 0) {
        #pragma unroll
        for (int s = 0; s < STG - 1; s++) {
            spin_ready(s, nb);
            mbar_expect_tx(mfull + s * 8, STAGE_B);
            bulk_g2s(sbase + s * STAGE_B,           gA + (size_t)s * A_STAGE, A_STAGE, mfull + s * 8);
            bulk_g2s(sbase + s * STAGE_B + A_STAGE, gB + (size_t)s * B_STAGE, B_STAGE, mfull + s * 8);
        }
    }

    int g = lane >> 3, sub = lane & 7;
    int rowA_base = wm * 64 + ((g & 1) << 3) + sub;
    int kcA_base  = g >> 1;
    int rowB_base = wn * 32 + ((g >> 1) << 3) + sub;
    int kcB_base  = g & 1;

    float acc[4][4][4];
    #pragma unroll
    for (int i = 0; i < 4; i++)
        #pragma unroll
        for (int j = 0; j < 4; j++)
            #pragma unroll
            for (int t = 0; t < 4; t++) acc[i][j][t] = 0.f;

    for (int k = 0; k < CHUNKS; k++) {
        int slot = k & 3;
        // producer: warp 0 refills stage k+STG-1
        if (wid == 0) {
            int kp = k + STG - 1;
            if (kp < CHUNKS) {
                int sp = kp & 3;
                if (kp >= STG) mbar_wait(mempty + sp * 8, ((kp >> 2) + 1) & 1);
                if (lane == 0) {
                    spin_ready(kp, nb);
                    mbar_expect_tx(mfull + sp * 8, STAGE_B);
                    bulk_g2s(sbase + sp * STAGE_B,           gA + (size_t)kp * A_STAGE, A_STAGE, mfull + sp * 8);
                    bulk_g2s(sbase + sp * STAGE_B + A_STAGE, gB + (size_t)kp * B_STAGE, B_STAGE, mfull + sp * 8);
                }
            }
        }

        mbar_wait(mfull + slot * 8, (k >> 2) & 1);

        uint32_t aS = sbase + slot * STAGE_B;
        uint32_t bS = aS + A_STAGE;
        #pragma unroll
        for (int ks = 0; ks < 4; ks++) {
            uint32_t afr[4][4], bfr[2][4];
            #pragma unroll
            for (int q = 0; q < 2; q++) {
                int row = rowB_base + q * 16;
                ldsm_x4(bfr[q], bS + sw_off(row, ks * 2 + kcB_base));
            }
            #pragma unroll
            for (int mt = 0; mt < 4; mt++) {
                int row = rowA_base + mt * 16;
                ldsm_x4(afr[mt], aS + sw_off(row, ks * 2 + kcA_base));
            }
            #pragma unroll
            for (int mt = 0; mt < 4; mt++)
                #pragma unroll
                for (int nt = 0; nt < 4; nt++)
                    mma16816(acc[mt][nt], afr[mt], &bfr[nt >> 1][(nt & 1) * 2]);
        }
        if (lane == 0) mbar_arrive(mempty + slot * 8);
    }

    // epilogue: bias + relu, write fp32 v
    int rlo = lane >> 2;
    int cpair = (lane & 3) * 2;
    int bn0 = nb * BN, bm0 = mb * BM;
    #pragma unroll
    for (int mt = 0; mt < 4; mt++) {
        #pragma unroll
        for (int nt = 0; nt < 4; nt++) {
            int col = bn0 + wn * 32 + nt * 8 + cpair;
            float b0 = __ldg(bv + col), b1 = __ldg(bv + col + 1);
            int row0 = bm0 + wm * 64 + mt * 16 + rlo;
            float2 o0, o1;
            o0.x = fmaxf(acc[mt][nt][0] + b0, 0.f);
            o0.y = fmaxf(acc[mt][nt][1] + b1, 0.f);
            o1.x = fmaxf(acc[mt][nt][2] + b0, 0.f);
            o1.y = fmaxf(acc[mt][nt][3] + b1, 0.f);
            *reinterpret_cast<float2*>(g_v + (size_t)row0 * HIDDEN + col) = o0;
            *reinterpret_cast<float2*>(g_v + (size_t)(row0 + 8) * HIDDEN + col) = o1;
        }
    }
}

// ==================== kernel 4: head  out = v @ Wo + bo ====================
__global__ void k_final(const float* __restrict__ Wo, const float* __restrict__ bo,
                        float* __restrict__ out) {
    int n = blockIdx.x, tid = threadIdx.x;
    float acc[CLASSES] = {};
    const float* vrow = g_v + (size_t)n * HIDDEN;
    for (int h = tid; h < HIDDEN; h += 256) {
        float vv = vrow[h];
        const float* wrow = Wo + (size_t)h * CLASSES;
        #pragma unroll
        for (int c = 0; c < CLASSES; c++) acc[c] = fmaf(vv, wrow[c], acc[c]);
    }
    #pragma unroll
    for (int c = 0; c < CLASSES; c++)
        #pragma unroll
        for (int o = 16; o > 0; o >>= 1)
            acc[c] += __shfl_xor_sync(0xffffffffu, acc[c], o);
    __shared__ float part[8][CLASSES];
    if ((tid & 31) == 0) {
        #pragma unroll
        for (int c = 0; c < CLASSES; c++) part[tid >> 5][c] = acc[c];
    }
    __syncthreads();
    if (tid < CLASSES) {
        float s = 0.f;
        #pragma unroll
        for (int w = 0; w < 8; w++) s += part[w][tid];
        out[(size_t)n * CLASSES + tid] = s + bo[tid];
    }
}

// ==================== launch ====================
extern "C" void kernel_launch(void* const* d_in, const int* in_sizes, int n_in,
                              void* d_out, int out_size) {
    const float* x  = (const float*)d_in[0];
    const float* Wu = (const float*)d_in[1];
    const float* bu = (const float*)d_in[2];
    const float* Wv = (const float*)d_in[3];
    const float* bv = (const float*)d_in[4];
    const float* Wo = (const float*)d_in[5];
    const float* bo = (const float*)d_in[6];
    float* out = (float*)d_out;

    // one-time setup on the (uncaptured) correctness call; reused during capture
    static cudaStream_t s2 = nullptr;
    static cudaEvent_t evF = nullptr, evJ = nullptr;
    static void* pReadyA = nullptr;
    static void* pReadyB = nullptr;
    if (!s2) {
        cudaStreamCreateWithFlags(&s2, cudaStreamNonBlocking);
        cudaEventCreateWithFlags(&evF, cudaEventDisableTiming);
        cudaEventCreateWithFlags(&evJ, cudaEventDisableTiming);
        cudaGetSymbolAddress(&pReadyA, g_ready_a);
        cudaGetSymbolAddress(&pReadyB, g_ready_b);
        cudaFuncSetAttribute(k_gemm, cudaFuncAttributeMaxDynamicSharedMemorySize, SMEM_GEMM);
    }

    // reset chunk-ready flags (graph replays reuse them)
    cudaMemsetAsync(pReadyA, 0, sizeof(int) * CHUNKS, 0);
    cudaMemsetAsync(pReadyB, 0, sizeof(int) * 8 * CHUNKS, 0);
    k_transpose_x<<<(N_SAMPLES * D_FEAT + 255) / 256, 256>>>(x);

    // fork: prep on s2, gemm on main stream; gemm producers spin on chunk flags
    cudaEventRecord(evF, 0);
    cudaStreamWaitEvent(s2, evF, 0);
    k_prep<<<PREP_BLOCKS, 256, 0, s2>>>(Wu, bu, Wv);
    k_gemm<<<dim3(HIDDEN / BN, N_SAMPLES / BM), 512, SMEM_GEMM>>>(bv);
    cudaEventRecord(evJ, s2);
    cudaStreamWaitEvent(0, evJ, 0);

    k_final<<<N_SAMPLES, 256>>>(Wo, bo, out);
}

// round 10
// speedup vs baseline: 1.0366x; 1.0366x over previous
#include <cuda_runtime.h>
#include <cuda_fp16.h>
#include <cstdint>

// Problem dims
#define N_SAMPLES 2048
#define D_FEAT    64
#define P_PAIRS   2016
#define INNER     32
#define KDIM      64512   // P_PAIRS * INNER
#define HIDDEN    2048
#define CLASSES   10

// GEMM tiling
#define BM 128
#define BN 256
#define BK 64
#define STG 4
#define CHUNKS (KDIM / BK)                 // 1008
#define A_STAGE (BM * 128)                 // 16384 B
#define B_STAGE (BN * 128)                 // 32768 B
#define STAGE_B (A_STAGE + B_STAGE)        // 49152 B
#define OFF_MBAR (STG * STAGE_B)           // 196608
#define SMEM_GEMM (OFF_MBAR + 64)
#define NCTAS 128

// -------------------- scratch (device globals; no allocation) --------------------
__device__ __half g_u [(size_t)N_SAMPLES * KDIM];   // tiled [mb][c][row][kc^sw]
__device__ __half g_bt[(size_t)HIDDEN    * KDIM];   // tiled [nb][c][row][kc^sw]
__device__ float  g_v [(size_t)N_SAMPLES * HIDDEN];
__device__ float  g_xT[(size_t)D_FEAT * N_SAMPLES];
__device__ int    g_ready[CHUNKS];                  // 1 = chunk's A+B slabs produced

// -------------------- helpers --------------------
__device__ __forceinline__ uint32_t smem_u32(const void* p) {
    return (uint32_t)__cvta_generic_to_shared(p);
}
__device__ __forceinline__ void mbar_init(uint32_t addr, uint32_t count) {
    asm volatile("mbarrier.init.shared.b64 [%0], %1;" :: "r"(addr), "r"(count) : "memory");
}
__device__ __forceinline__ void mbar_expect_tx(uint32_t addr, uint32_t bytes) {
    asm volatile("mbarrier.arrive.expect_tx.shared.b64 _, [%0], %1;"
                 :: "r"(addr), "r"(bytes) : "memory");
}
__device__ __forceinline__ void mbar_arrive(uint32_t addr) {
    asm volatile("mbarrier.arrive.shared.b64 _, [%0];" :: "r"(addr) : "memory");
}
__device__ __forceinline__ void mbar_wait(uint32_t addr, uint32_t parity) {
    uint32_t done;
    asm volatile(
        "{\n\t.reg .pred p;\n\t"
        "mbarrier.try_wait.parity.acquire.cta.shared::cta.b64 p, [%1], %2;\n\t"
        "selp.b32 %0, 1, 0, p;\n\t}"
        : "=r"(done) : "r"(addr), "r"(parity) : "memory");
    if (!done) {
        asm volatile(
            "{\n\t.reg .pred P1;\n\t"
            "W_%=:\n\t"
            "mbarrier.try_wait.parity.acquire.cta.shared::cta.b64 P1, [%0], %1, 0x989680;\n\t"
            "@P1 bra.uni D_%=;\n\t"
            "bra.uni W_%=;\n\t"
            "D_%=:\n\t}"
            :: "r"(addr), "r"(parity) : "memory");
    }
}
__device__ __forceinline__ void bulk_g2s(uint32_t dstSmem, const void* srcGmem,
                                         uint32_t bytes, uint32_t mbar) {
    asm volatile(
        "cp.async.bulk.shared::cluster.global.mbarrier::complete_tx::bytes [%0], [%1], %2, [%3];"
        :: "r"(dstSmem), "l"(srcGmem), "r"(bytes), "r"(mbar) : "memory");
}
__device__ __forceinline__ void ldsm_x4(uint32_t* r, uint32_t addr) {
    asm volatile("ldmatrix.sync.aligned.m8n8.x4.shared.b16 {%0,%1,%2,%3}, [%4];"
                 : "=r"(r[0]), "=r"(r[1]), "=r"(r[2]), "=r"(r[3]) : "r"(addr));
}
__device__ __forceinline__ void mma16816(float* c, const uint32_t* a, const uint32_t* b) {
    asm volatile(
        "mma.sync.aligned.m16n8k16.row.col.f32.f16.f16.f32 "
        "{%0,%1,%2,%3}, {%4,%5,%6,%7}, {%8,%9}, {%0,%1,%2,%3};"
        : "+f"(c[0]), "+f"(c[1]), "+f"(c[2]), "+f"(c[3])
        : "r"(a[0]), "r"(a[1]), "r"(a[2]), "r"(a[3]), "r"(b[0]), "r"(b[1]));
}
__device__ __forceinline__ uint32_t sw_off(int row, int kc) {
    return (uint32_t)(row * 128 + ((kc ^ (row & 7)) << 4));
}
__device__ __forceinline__ void spin_ready(int c) {
    volatile int* r = g_ready + c;
    while (*r == 0) __nanosleep(64);
    __threadfence();
}

// ==================== kernel 1: transpose x ====================
__global__ void k_transpose_x(const float* __restrict__ x) {
    int idx = blockIdx.x * blockDim.x + threadIdx.x;
    if (idx < N_SAMPLES * D_FEAT) {
        int n = idx >> 6, d = idx & 63;
        g_xT[(size_t)d * N_SAMPLES + n] = x[idx];
    }
}

// ==================== kernel 2: GEMM with fused phase-0 prep ====================
// Phase 0: each CTA (L of 128) preps chunks L, L+128, ... (pairwise MLP -> g_u,
//          Wv transpose/convert -> g_bt), publishing g_ready[c].
// Phase 1: R6 GEMM — 16 warps 64x32 tiles, warp0/lane0 bulk-TMA producer spinning
//          on g_ready, 4-stage mbarrier pipeline, no mainloop syncthreads.
__global__ void __launch_bounds__(512, 1) k_gemm(const float* __restrict__ Wu,
                                                 const float* __restrict__ bu,
                                                 const float* __restrict__ Wv,
                                                 const float* __restrict__ bv) {
    extern __shared__ char smem[];
    __shared__ float s_tile[32][129];       // conv transpose scratch
    __shared__ float s_pw[2][3][INNER];     // pair weights: [pair][w0/w1/bias][i]

    uint32_t sbase = smem_u32(smem);
    int tid = threadIdx.x;
    int lane = tid & 31;
    int wid = tid >> 5;          // 0..15
    int nb = blockIdx.x;         // 8 n-blocks
    int mb = blockIdx.y;         // 16 m-blocks
    int L = mb * 8 + nb;         // 0..127

    // ---------------- phase 0: prep my chunks ----------------
    uint4* g_u_u4 = reinterpret_cast<uint4*>(g_u);
    for (int c = L; c < CHUNKS; c += NCTAS) {
        // -- A: pairs 2c, 2c+1 over all samples --
        if (tid < 2 * INNER) {
            int pp = tid >> 5, i = tid & 31;
            int p = c * 2 + pp;
            s_pw[pp][0][i] = Wu[(size_t)p * 64 + i];
            s_pw[pp][1][i] = Wu[(size_t)p * 64 + 32 + i];
            s_pw[pp][2][i] = bu[(size_t)p * 32 + i];
        }
        __syncthreads();
        // pair indices for 2c and 2c+1
        int pa[2], pb[2];
        #pragma unroll
        for (int pp = 0; pp < 2; pp++) {
            int p = c * 2 + pp;
            int a = 0, rem = p;
            while (rem >= (D_FEAT - 1 - a)) { rem -= (D_FEAT - 1 - a); a++; }
            pa[pp] = a; pb[pp] = a + 1 + rem;
        }
        #pragma unroll 1
        for (int s = 0; s < 4; s++) {
            int n = tid + s * 512;
            uint4 outs[8];
            #pragma unroll
            for (int pp = 0; pp < 2; pp++) {
                float va = g_xT[(size_t)pa[pp] * N_SAMPLES + n];
                float vb = g_xT[(size_t)pb[pp] * N_SAMPLES + n];
                __half2 ov[INNER / 2];
                #pragma unroll
                for (int i = 0; i < INNER; i += 2) {
                    float r0 = fmaf(va, s_pw[pp][0][i],     fmaf(vb, s_pw[pp][1][i],     s_pw[pp][2][i]));
                    float r1 = fmaf(va, s_pw[pp][0][i + 1], fmaf(vb, s_pw[pp][1][i + 1], s_pw[pp][2][i + 1]));
                    ov[i / 2] = __floats2half2_rn(fmaxf(r0, 0.f), fmaxf(r1, 0.f));
                }
                const uint4* src = reinterpret_cast<const uint4*>(ov);
                outs[pp * 4 + 0] = src[0]; outs[pp * 4 + 1] = src[1];
                outs[pp * 4 + 2] = src[2]; outs[pp * 4 + 3] = src[3];
            }
            int mbb = n >> 7, row = n & 127;
            size_t base8 = ((size_t)(mbb * CHUNKS + c) * 128 + row) * 8;
            #pragma unroll
            for (int kc = 0; kc < 8; kc++)
                g_u_u4[base8 + (kc ^ (row & 7))] = outs[kc];
        }
        // -- B: Wv[64c..64c+64)[0..2048) fp32 -> fp16 transposed --
        #pragma unroll 1
        for (int it = 0; it < 32; it++) {
            int kt0 = c * 64 + (it & 1) * 32;
            int nt0 = (it >> 1) * 128;
            __syncthreads();
            #pragma unroll
            for (int pass = 0; pass < 8; pass++) {
                int idx = tid + pass * 512;
                int kl = idx >> 7, nl = idx & 127;
                s_tile[kl][nl] = Wv[(size_t)(kt0 + kl) * HIDDEN + nt0 + nl];
            }
            __syncthreads();
            int nl = tid >> 2, uq = tid & 3;
            __half hp[8];
            #pragma unroll
            for (int j = 0; j < 8; j++) hp[j] = __float2half(s_tile[uq * 8 + j][nl]);
            int n = nt0 + nl;
            int nbb = n >> 8, rowB = n & 255;
            int kcq = ((kt0 & 63) >> 3) + uq;
            size_t unit = ((size_t)(nbb * CHUNKS + c) * 256 + rowB) * 8 + (kcq ^ (rowB & 7));
            reinterpret_cast<uint4*>(g_bt)[unit] = *reinterpret_cast<uint4*>(hp);
        }
        __threadfence();
        __syncthreads();
        if (tid == 0) atomicExch(&g_ready[c], 1);
    }

    // ---------------- phase 1: GEMM (R6 structure) ----------------
    int wm = wid >> 3;           // 0..1  (64 rows each)
    int wn = wid & 7;            // 0..7  (32 cols each)

    const char* gA = (const char*)g_u  + (size_t)mb * CHUNKS * A_STAGE;
    const char* gB = (const char*)g_bt + (size_t)nb * CHUNKS * B_STAGE;

    uint32_t mfull = sbase + OFF_MBAR;
    uint32_t mempty = sbase + OFF_MBAR + 32;
    if (tid == 0) {
        #pragma unroll
        for (int s = 0; s < STG; s++) {
            mbar_init(mfull + s * 8, 1);
            mbar_init(mempty + s * 8, 16);
        }
    }
    __syncthreads();

    if (tid == 0) {
        #pragma unroll
        for (int s = 0; s < STG - 1; s++) {
            spin_ready(s);
            mbar_expect_tx(mfull + s * 8, STAGE_B);
            bulk_g2s(sbase + s * STAGE_B,           gA + (size_t)s * A_STAGE, A_STAGE, mfull + s * 8);
            bulk_g2s(sbase + s * STAGE_B + A_STAGE, gB + (size_t)s * B_STAGE, B_STAGE, mfull + s * 8);
        }
    }

    int g = lane >> 3, sub = lane & 7;
    int rowA_base = wm * 64 + ((g & 1) << 3) + sub;
    int kcA_base  = g >> 1;
    int rowB_base = wn * 32 + ((g >> 1) << 3) + sub;
    int kcB_base  = g & 1;

    float acc[4][4][4];
    #pragma unroll
    for (int i = 0; i < 4; i++)
        #pragma unroll
        for (int j = 0; j < 4; j++)
            #pragma unroll
            for (int t = 0; t < 4; t++) acc[i][j][t] = 0.f;

    for (int k = 0; k < CHUNKS; k++) {
        int slot = k & 3;
        if (wid == 0) {
            int kp = k + STG - 1;
            if (kp < CHUNKS) {
                int sp = kp & 3;
                if (kp >= STG) mbar_wait(mempty + sp * 8, ((kp >> 2) + 1) & 1);
                if (lane == 0) {
                    spin_ready(kp);
                    mbar_expect_tx(mfull + sp * 8, STAGE_B);
                    bulk_g2s(sbase + sp * STAGE_B,           gA + (size_t)kp * A_STAGE, A_STAGE, mfull + sp * 8);
                    bulk_g2s(sbase + sp * STAGE_B + A_STAGE, gB + (size_t)kp * B_STAGE, B_STAGE, mfull + sp * 8);
                }
            }
        }

        mbar_wait(mfull + slot * 8, (k >> 2) & 1);

        uint32_t aS = sbase + slot * STAGE_B;
        uint32_t bS = aS + A_STAGE;
        #pragma unroll
        for (int ks = 0; ks < 4; ks++) {
            uint32_t afr[4][4], bfr[2][4];
            #pragma unroll
            for (int q = 0; q < 2; q++) {
                int row = rowB_base + q * 16;
                ldsm_x4(bfr[q], bS + sw_off(row, ks * 2 + kcB_base));
            }
            #pragma unroll
            for (int mt = 0; mt < 4; mt++) {
                int row = rowA_base + mt * 16;
                ldsm_x4(afr[mt], aS + sw_off(row, ks * 2 + kcA_base));
            }
            #pragma unroll
            for (int mt = 0; mt < 4; mt++)
                #pragma unroll
                for (int nt = 0; nt < 4; nt++)
                    mma16816(acc[mt][nt], afr[mt], &bfr[nt >> 1][(nt & 1) * 2]);
        }
        if (lane == 0) mbar_arrive(mempty + slot * 8);
    }

    // epilogue: bias + relu, write fp32 v
    int rlo = lane >> 2;
    int cpair = (lane & 3) * 2;
    int bn0 = nb * BN, bm0 = mb * BM;
    #pragma unroll
    for (int mt = 0; mt < 4; mt++) {
        #pragma unroll
        for (int nt = 0; nt < 4; nt++) {
            int col = bn0 + wn * 32 + nt * 8 + cpair;
            float b0 = __ldg(bv + col), b1 = __ldg(bv + col + 1);
            int row0 = bm0 + wm * 64 + mt * 16 + rlo;
            float2 o0, o1;
            o0.x = fmaxf(acc[mt][nt][0] + b0, 0.f);
            o0.y = fmaxf(acc[mt][nt][1] + b1, 0.f);
            o1.x = fmaxf(acc[mt][nt][2] + b0, 0.f);
            o1.y = fmaxf(acc[mt][nt][3] + b1, 0.f);
            *reinterpret_cast<float2*>(g_v + (size_t)row0 * HIDDEN + col) = o0;
            *reinterpret_cast<float2*>(g_v + (size_t)(row0 + 8) * HIDDEN + col) = o1;
        }
    }
}

// ==================== kernel 3: head  out = v @ Wo + bo ====================
__global__ void k_final(const float* __restrict__ Wo, const float* __restrict__ bo,
                        float* __restrict__ out) {
    int n = blockIdx.x, tid = threadIdx.x;
    float acc[CLASSES] = {};
    const float* vrow = g_v + (size_t)n * HIDDEN;
    for (int h = tid; h < HIDDEN; h += 256) {
        float vv = vrow[h];
        const float* wrow = Wo + (size_t)h * CLASSES;
        #pragma unroll
        for (int c = 0; c < CLASSES; c++) acc[c] = fmaf(vv, wrow[c], acc[c]);
    }
    #pragma unroll
    for (int c = 0; c < CLASSES; c++)
        #pragma unroll
        for (int o = 16; o > 0; o >>= 1)
            acc[c] += __shfl_xor_sync(0xffffffffu, acc[c], o);
    __shared__ float part[8][CLASSES];
    if ((tid & 31) == 0) {
        #pragma unroll
        for (int c = 0; c < CLASSES; c++) part[tid >> 5][c] = acc[c];
    }
    __syncthreads();
    if (tid < CLASSES) {
        float s = 0.f;
        #pragma unroll
        for (int w = 0; w < 8; w++) s += part[w][tid];
        out[(size_t)n * CLASSES + tid] = s + bo[tid];
    }
}

// ==================== launch ====================
extern "C" void kernel_launch(void* const* d_in, const int* in_sizes, int n_in,
                              void* d_out, int out_size) {
    const float* x  = (const float*)d_in[0];
    const float* Wu = (const float*)d_in[1];
    const float* bu = (const float*)d_in[2];
    const float* Wv = (const float*)d_in[3];
    const float* bv = (const float*)d_in[4];
    const float* Wo = (const float*)d_in[5];
    const float* bo = (const float*)d_in[6];
    float* out = (float*)d_out;

    static void* pReady = nullptr;
    if (!pReady) {
        cudaGetSymbolAddress(&pReady, g_ready);
        cudaFuncSetAttribute(k_gemm, cudaFuncAttributeMaxDynamicSharedMemorySize, SMEM_GEMM);
    }

    cudaMemsetAsync(pReady, 0, sizeof(int) * CHUNKS, 0);
    k_transpose_x<<<(N_SAMPLES * D_FEAT + 255) / 256, 256>>>(x);
    k_gemm<<<dim3(HIDDEN / BN, N_SAMPLES / BM), 512, SMEM_GEMM>>>(Wu, bu, Wv, bv);
    k_final<<<N_SAMPLES, 256>>>(Wo, bo, out);
}